// round 1
// baseline (speedup 1.0000x reference)
#include <cuda_runtime.h>
#include <cuda_bf16.h>
#include <math.h>

// Problem constants: B=2, L=512 (both sides), Dh=1024, P=64, C = 4P+1 = 257
#define NB    2
#define LSEQ  512
#define DH    1024
#define PP    64
#define NCH   257
#define PLANE (LSEQ*LSEQ)      // 262144 floats per channel plane
#define PLANE4 (PLANE/4)       // 65536 float4
#define NROWS (NB*LSEQ)        // 1024 rows per side

// Scratch (device globals; no allocation allowed)
__device__ float g_za [NB*LSEQ*PP];   // [b][i][p]  row-major
__device__ float g_zbT[NB*PP*LSEQ];   // [b][p][j]  transposed
__device__ float g_na [NROWS];
__device__ float g_nb [NROWS];

__device__ __forceinline__ float gelu_exact(float x) {
    // 0.5 * x * (1 + erf(x / sqrt(2)))
    return 0.5f * x * (1.0f + erff(x * 0.7071067811865476f));
}

// ---------------------------------------------------------------------------
// Kernel A: z = GELU(h @ W + bias), per-row L2 norm, and (side b) transpose.
// blockDim (16, 8): tx = p-quad (4 consecutive p via float4 W loads),
//                   ty = row within the 8-row block tile.
// grid (128, 2): 128 row-groups per side, side in blockIdx.y.
// ---------------------------------------------------------------------------
__global__ __launch_bounds__(128) void proj_kernel(
    const float* __restrict__ h_a, const float* __restrict__ h_b,
    const float* __restrict__ Wa,  const float* __restrict__ ba,
    const float* __restrict__ Wb,  const float* __restrict__ bb)
{
    const int side = blockIdx.y;                 // 0 = a, 1 = b
    const float* __restrict__ H  = side ? h_b : h_a;
    const float* __restrict__ Wp = side ? Wb  : Wa;
    const float* __restrict__ bp = side ? bb  : ba;

    const int tx = threadIdx.x;                  // 0..15 (p-quad)
    const int ty = threadIdx.y;                  // 0..7  (row in tile)
    const int tid = ty * 16 + tx;
    const int rowBase = blockIdx.x * 8;          // first row of this tile

    // h tile in shared, padded row pitch to kill bank conflicts on float4 reads
    // pitch = 1028 floats = 257 float4 (257 mod 32 != 0 for float, fine for f4)
    __shared__ float h_s[8 * 1028];
    {
        const float4* __restrict__ H4 = (const float4*)H;
        float4* hs4 = (float4*)h_s;
        // 8 rows * 256 float4 = 2048 float4, 128 threads -> 16 each
        #pragma unroll
        for (int it = 0; it < 16; ++it) {
            int idx = tid + it * 128;            // 0..2047
            int r   = idx >> 8;                  // row in tile
            int c4  = idx & 255;                 // float4 col
            hs4[r * 257 + c4] = H4[(size_t)rowBase * 256 + idx];
        }
    }
    __syncthreads();

    const float4* __restrict__ W4 = (const float4*)Wp;   // [1024][16] float4
    const float4* hs4row = ((const float4*)h_s) + ty * 257;

    float4 acc = make_float4(0.f, 0.f, 0.f, 0.f);
    #pragma unroll 4
    for (int k4 = 0; k4 < 256; ++k4) {
        float4 h4 = hs4row[k4];
        float4 w0 = W4[(4*k4 + 0) * 16 + tx];
        float4 w1 = W4[(4*k4 + 1) * 16 + tx];
        float4 w2 = W4[(4*k4 + 2) * 16 + tx];
        float4 w3 = W4[(4*k4 + 3) * 16 + tx];
        acc.x += h4.x*w0.x; acc.y += h4.x*w0.y; acc.z += h4.x*w0.z; acc.w += h4.x*w0.w;
        acc.x += h4.y*w1.x; acc.y += h4.y*w1.y; acc.z += h4.y*w1.z; acc.w += h4.y*w1.w;
        acc.x += h4.z*w2.x; acc.y += h4.z*w2.y; acc.z += h4.z*w2.z; acc.w += h4.z*w2.w;
        acc.x += h4.w*w3.x; acc.y += h4.w*w3.y; acc.z += h4.w*w3.z; acc.w += h4.w*w3.w;
    }

    const float4 bias4 = ((const float4*)bp)[tx];
    float4 z;
    z.x = gelu_exact(acc.x + bias4.x);
    z.y = gelu_exact(acc.y + bias4.y);
    z.z = gelu_exact(acc.z + bias4.z);
    z.w = gelu_exact(acc.w + bias4.w);

    // per-row sum of squares, reduced over the 16 p-quad lanes (width-16 shfl)
    float ss = z.x*z.x + z.y*z.y + z.z*z.z + z.w*z.w;
    ss += __shfl_xor_sync(0xFFFFFFFFu, ss, 1, 16);
    ss += __shfl_xor_sync(0xFFFFFFFFu, ss, 2, 16);
    ss += __shfl_xor_sync(0xFFFFFFFFu, ss, 4, 16);
    ss += __shfl_xor_sync(0xFFFFFFFFu, ss, 8, 16);

    const int row = rowBase + ty;                // 0..1023 within side
    if (side == 0) {
        ((float4*)g_za)[row * 16 + tx] = z;
        if (tx == 0) g_na[row] = sqrtf(ss + 1e-8f);
    } else {
        const int b = row >> 9;
        const int j = row & 511;
        const int p0 = tx * 4;
        float* dst = g_zbT + ((size_t)(b * PP + p0)) * LSEQ + j;
        dst[0*LSEQ] = z.x;
        dst[1*LSEQ] = z.y;
        dst[2*LSEQ] = z.z;
        dst[3*LSEQ] = z.w;
        if (tx == 0) g_nb[row] = sqrtf(ss + 1e-8f);
    }
}

// ---------------------------------------------------------------------------
// Kernel B: writes the full [B, 257, LA, LB] output. One block per (i, b).
// 128 threads, each owns 4 consecutive j (float4 stores). Per channel p:
// one coalesced LDG.128 of zbT row + four STG.128 streaming stores; dot (for
// the cosine channel) accumulated in-register for free.
// ---------------------------------------------------------------------------
__global__ __launch_bounds__(128) void interact_kernel(float* __restrict__ out)
{
    const int i = blockIdx.x;       // 0..511
    const int b = blockIdx.y;       // 0..1
    const int t = threadIdx.x;      // 0..127, covers j = 4t .. 4t+3

    __shared__ float za_s[PP];
    __shared__ float na_s;
    if (t < PP) za_s[t] = g_za[((size_t)(b * LSEQ + i)) * PP + t];
    if (t == 0) na_s = g_na[b * LSEQ + i];
    __syncthreads();

    const float4 nb4 = *(const float4*)&g_nb[b * LSEQ + 4 * t];

    float4* O = ((float4*)out) + (size_t)b * NCH * PLANE4 + (size_t)i * (LSEQ/4) + t;
    const float4* ZBT = ((const float4*)(g_zbT + (size_t)b * PP * LSEQ)) + t;

    float4 dot = make_float4(0.f, 0.f, 0.f, 0.f);

    #pragma unroll 4
    for (int p = 0; p < PP; ++p) {
        float4 zb = __ldg(ZBT + p * (LSEQ/4));
        float  za = za_s[p];
        float4* o = O + (size_t)p * PLANE4;

        __stcs(o,                          make_float4(za, za, za, za));
        __stcs(o + (size_t) 64 * PLANE4,   zb);
        __stcs(o + (size_t)128 * PLANE4,
               make_float4(fabsf(za - zb.x), fabsf(za - zb.y),
                           fabsf(za - zb.z), fabsf(za - zb.w)));
        __stcs(o + (size_t)192 * PLANE4,
               make_float4(za * zb.x, za * zb.y, za * zb.z, za * zb.w));

        dot.x += za * zb.x; dot.y += za * zb.y;
        dot.z += za * zb.z; dot.w += za * zb.w;
    }

    const float inv_na = 1.0f / na_s;
    float4 sim = make_float4(dot.x * inv_na / nb4.x,
                             dot.y * inv_na / nb4.y,
                             dot.z * inv_na / nb4.z,
                             dot.w * inv_na / nb4.w);
    __stcs(O + (size_t)256 * PLANE4, sim);
}

extern "C" void kernel_launch(void* const* d_in, const int* in_sizes, int n_in,
                              void* d_out, int out_size)
{
    const float* h_a = (const float*)d_in[0];
    const float* h_b = (const float*)d_in[1];
    const float* Wa  = (const float*)d_in[2];
    const float* ba  = (const float*)d_in[3];
    const float* Wb  = (const float*)d_in[4];
    const float* bb  = (const float*)d_in[5];
    float* out = (float*)d_out;

    proj_kernel<<<dim3(128, 2), dim3(16, 8)>>>(h_a, h_b, Wa, ba, Wb, bb);
    interact_kernel<<<dim3(LSEQ, NB), 128>>>(out);
}